// round 5
// baseline (speedup 1.0000x reference)
#include <cuda_runtime.h>
#include <math.h>

typedef unsigned long long ull;

#define Bb 64
#define Tt 1024
#define Ii 256
#define Hh 512
#define Gg 2048

// ---- scratch (device globals) ----
__device__ float g_xT[(size_t)Tt * Ii * Bb];
__device__ float g_XP[(size_t)Tt * Gg * Bb];
__device__ float g_OUT0[(size_t)Tt * Hh * Bb];
__device__ float g_h[2][Hh * Bb];
__device__ volatile unsigned g_bar;

__device__ __forceinline__ ull ffma2(ull a, ull b, ull c) {
    ull d;
    asm("fma.rn.f32x2 %0, %1, %2, %3;" : "=l"(d) : "l"(a), "l"(b), "l"(c));
    return d;
}
__device__ __forceinline__ ull splat2(float v) {
    ull d;
    asm("mov.b64 %0, {%1, %1};" : "=l"(d) : "f"(v));
    return d;
}
__device__ __forceinline__ float sigf(float x) { return 1.0f / (1.0f + __expf(-x)); }

// ---- transpose x[b][i][t] -> g_xT[t][i][b] ----
__global__ void k_trx(const float* __restrict__ x) {
    __shared__ float tile[32][33];
    int t0 = blockIdx.x * 32, b0 = blockIdx.y * 32, i = blockIdx.z;
    int tx = threadIdx.x, ty = threadIdx.y;
    tile[ty][tx] = x[((size_t)(b0 + ty) * Ii + i) * Tt + t0 + tx];
    __syncthreads();
    g_xT[((size_t)(t0 + ty) * Ii + i) * Bb + b0 + tx] = tile[tx][ty];
}

// ---- out transpose: g_OUT0[t][h][b] -> out[b][t][h] ----
__global__ void k_tro(float* __restrict__ out) {
    __shared__ float tile[32][33];
    int h0 = blockIdx.x * 32, b0 = blockIdx.y * 32, t = blockIdx.z;
    int tx = threadIdx.x, ty = threadIdx.y;
    tile[ty][tx] = g_OUT0[((size_t)t * Hh + h0 + ty) * Bb + b0 + tx];
    __syncthreads();
    out[((size_t)(b0 + ty) * Tt + t) * Hh + h0 + tx] = tile[tx][ty];
}

// ---- input GEMM: XP[t][g][b] = sum_k W[g][k]*X[t][k][b] + bih[g]+bhh[g] ----
// block: 128 g-rows x (2 t x 64 b). BK=8. 256 thr, 8x8 micro (f32x2).
__global__ void __launch_bounds__(256) k_gemm(const float* __restrict__ W,
                                              const float* __restrict__ bih,
                                              const float* __restrict__ bhh,
                                              const float* __restrict__ X, int K) {
    const int g0 = blockIdx.x * 128, t0 = blockIdx.y * 2;
    __shared__ float As[2][8][264];
    __shared__ float Bs[2][8][128];
    const int tid = threadIdx.x;
    const int rg = tid >> 4, cg = tid & 15;
    const int ar = tid >> 1, ak = (tid & 1) * 4;
    const int bkk = tid >> 5, bc = (tid & 31) * 4;
    const int btb = bc >> 6, bcb = bc & 63;
    const float* Arow = W + (size_t)(g0 + ar) * K + ak;
    const float* Bsrc = X + ((size_t)(t0 + btb) * K + bkk) * Bb + bcb;

    ull acc[8][4];
#pragma unroll
    for (int i = 0; i < 8; i++)
#pragma unroll
        for (int p = 0; p < 4; p++) acc[i][p] = 0ull;

    {
        float4 w4 = *(const float4*)(Arow);
#pragma unroll
        for (int jj = 0; jj < 4; jj++) {
            float v = ((const float*)&w4)[jj];
            *(float2*)&As[0][ak + jj][2 * ar] = make_float2(v, v);
        }
        *(float4*)&Bs[0][bkk][bc] = *(const float4*)(Bsrc);
    }
    __syncthreads();

    const int nk = K >> 3;
    for (int kc = 0; kc < nk; kc++) {
        const int cur = kc & 1;
        float4 w4n, b4n;
        if (kc + 1 < nk) {
            w4n = *(const float4*)(Arow + (kc + 1) * 8);
            b4n = *(const float4*)(Bsrc + (size_t)(kc + 1) * 8 * Bb);
        }
#pragma unroll
        for (int kk = 0; kk < 8; kk++) {
            ulonglong2 q0 = *(const ulonglong2*)&As[cur][kk][16 * rg];
            ulonglong2 q1 = *(const ulonglong2*)&As[cur][kk][16 * rg + 4];
            ulonglong2 q2 = *(const ulonglong2*)&As[cur][kk][16 * rg + 8];
            ulonglong2 q3 = *(const ulonglong2*)&As[cur][kk][16 * rg + 12];
            ulonglong2 u0 = *(const ulonglong2*)&Bs[cur][kk][8 * cg];
            ulonglong2 u1 = *(const ulonglong2*)&Bs[cur][kk][8 * cg + 4];
            ull a8[8] = {q0.x, q0.y, q1.x, q1.y, q2.x, q2.y, q3.x, q3.y};
            ull b4[4] = {u0.x, u0.y, u1.x, u1.y};
#pragma unroll
            for (int i = 0; i < 8; i++)
#pragma unroll
                for (int p = 0; p < 4; p++) acc[i][p] = ffma2(a8[i], b4[p], acc[i][p]);
        }
        if (kc + 1 < nk) {
            const int nxt = cur ^ 1;
#pragma unroll
            for (int jj = 0; jj < 4; jj++) {
                float v = ((const float*)&w4n)[jj];
                *(float2*)&As[nxt][ak + jj][2 * ar] = make_float2(v, v);
            }
            *(float4*)&Bs[nxt][bkk][bc] = b4n;
        }
        __syncthreads();
    }

#pragma unroll
    for (int i = 0; i < 8; i++) {
        const int grow = g0 + rg * 8 + i;
        const float bias = bih[grow] + bhh[grow];
#pragma unroll
        for (int p = 0; p < 4; p++) {
            float2 v = *(float2*)&acc[i][p];
            v.x += bias; v.y += bias;
            const int c = cg * 8 + 2 * p;
            *(float2*)(g_XP + ((size_t)(t0 + (c >> 6)) * Gg + grow) * Bb + (c & 63)) = v;
        }
    }
}

// ---- reset: barrier + h0 ----
__global__ void k_reset() {
    int tid = blockIdx.x * blockDim.x + threadIdx.x;
    if (tid == 0) g_bar = 0u;
    if (tid < Hh * Bb) g_h[0][tid] = 0.0f;
}

// ---- persistent recurrence: 128 blocks x 256 thr ----
// block j owns h-idx [4j,4j+4): local row r = q*4+hh -> gate row q*512 + 4j + hh.
// thread: kq = tid>>6 (k-split of 4), b = tid&63. 8 accs = row-pairs.
__global__ void __launch_bounds__(256) k_rec(const float* __restrict__ Whh,
                                             float* __restrict__ slab,
                                             float* __restrict__ dout, int layer) {
    extern __shared__ float sm[];
    float* Wt = sm;              // [512][16]
    float* red = sm + 8192;      // [4][64][17]
    const int tid = threadIdx.x;
    const int j = blockIdx.x;
    const int kq = tid >> 6, b = tid & 63;
    const int hh = kq;           // activation role reuses split

    for (int idx = tid; idx < 8192; idx += 256) {
        int r = idx & 15, k = idx >> 4;
        Wt[idx] = Whh[(size_t)((r >> 2) * Hh + j * 4 + (r & 3)) * Hh + k];
    }
    __syncthreads();

    const int kb = kq * 128;
    float c_reg = 0.0f;
    float* outHid = dout + (size_t)Bb * Tt * Hh + (size_t)layer * Bb * Hh;
    float* outCell = outHid + 2 * (size_t)Bb * Hh;

    for (int t = 0; t < Tt; t++) {
        const float* hR = g_h[t & 1];
        const float* xpt = g_XP + (size_t)t * Gg * Bb;
        ull acc[8];
#pragma unroll
        for (int i = 0; i < 8; i++) acc[i] = 0ull;

        for (int gblk = 0; gblk < 16; gblk++) {
            float hv[8];
#pragma unroll
            for (int u = 0; u < 8; u++)
                hv[u] = __ldcg(&hR[(kb + gblk * 8 + u) * Bb + b]);
#pragma unroll
            for (int u = 0; u < 8; u++) {
                ull hp = splat2(hv[u]);
                const float* wk = Wt + (kb + gblk * 8 + u) * 16;
#pragma unroll
                for (int i = 0; i < 4; i++) {
                    ulonglong2 w2 = *(const ulonglong2*)(wk + 4 * i);
                    acc[2 * i] = ffma2(w2.x, hp, acc[2 * i]);
                    acc[2 * i + 1] = ffma2(w2.y, hp, acc[2 * i + 1]);
                }
            }
        }
        // store partials: red[kq][b][r], r = 0..15 (pad 17)
        {
            float* rp = red + (kq * 64 + b) * 17;
            const float* af = (const float*)acc;
#pragma unroll
            for (int r = 0; r < 16; r++) rp[r] = af[r];
        }
        __syncthreads();

        // activation: thread (hh, b)
        float gv[4];
#pragma unroll
        for (int q = 0; q < 4; q++) {
            float s = xpt[(size_t)(q * Hh + j * 4 + hh) * Bb + b];
#pragma unroll
            for (int k2 = 0; k2 < 4; k2++) s += red[(k2 * 64 + b) * 17 + q * 4 + hh];
            gv[q] = s;
        }
        float ig = sigf(gv[0]), fg = sigf(gv[1]);
        float gg = tanhf(gv[2]), og = sigf(gv[3]);
        c_reg = fg * c_reg + ig * gg;
        float hval = og * tanhf(c_reg);
        const int hi = j * 4 + hh;
        __stcg(&g_h[(t + 1) & 1][hi * Bb + b], hval);
        __stcg(&slab[((size_t)t * Hh + hi) * Bb + b], hval);
        if (t == Tt - 1) {
            outHid[(size_t)b * Hh + hi] = hval;
            outCell[(size_t)b * Hh + hi] = c_reg;
        }

        // grid barrier (monotonic)
        __syncthreads();
        if (tid == 0) {
            __threadfence();
            atomicAdd((unsigned*)&g_bar, 1u);
            unsigned tgt = 128u * (unsigned)(t + 1) + (layer ? 128u * Tt : 0u) * 0u;
            while (g_bar < 128u * (unsigned)(t + 1)) { }
            (void)tgt;
            __threadfence();
        }
        __syncthreads();
    }
}

extern "C" void kernel_launch(void* const* d_in, const int* in_sizes, int n_in,
                              void* d_out, int out_size) {
    const float* x = (const float*)d_in[0];
    const float* Wih0 = (const float*)d_in[1];
    const float* Whh0 = (const float*)d_in[2];
    const float* bih0 = (const float*)d_in[3];
    const float* bhh0 = (const float*)d_in[4];
    const float* Wih1 = (const float*)d_in[5];
    const float* Whh1 = (const float*)d_in[6];
    const float* bih1 = (const float*)d_in[7];
    const float* bhh1 = (const float*)d_in[8];
    float* out = (float*)d_out;

    float *xT, *out0;
    cudaGetSymbolAddress((void**)&xT, g_xT);
    cudaGetSymbolAddress((void**)&out0, g_OUT0);

    const int recSmem = (8192 + 4 * 64 * 17) * 4;
    cudaFuncSetAttribute(k_rec, cudaFuncAttributeMaxDynamicSharedMemorySize, recSmem);

    dim3 thr32(32, 32);

    // layer 0
    k_trx<<<dim3(Tt / 32, Bb / 32, Ii), thr32>>>(x);
    k_gemm<<<dim3(Gg / 128, Tt / 2), 256>>>(Wih0, bih0, bhh0, xT, Ii);
    k_reset<<<128, 256>>>();
    k_rec<<<128, 256, recSmem>>>(Whh0, out0, out, 0);

    // layer 1
    k_gemm<<<dim3(Gg / 128, Tt / 2), 256>>>(Wih1, bih1, bhh1, out0, Hh);
    k_reset<<<128, 256>>>();
    k_rec<<<128, 256, recSmem>>>(Whh1, out0, out, 1);

    // final transpose to out[b][t][h]
    k_tro<<<dim3(Hh / 32, Bb / 32, Tt), thr32>>>(out);
}